// round 2
// baseline (speedup 1.0000x reference)
#include <cuda_runtime.h>
#include <math.h>
#include <stdint.h>

// Problem constants
#define DIMM   768
#define NHEAD  12
#define HDIM   64
#define BATCH  2
#define GRID_H 48
#define NSEQ   2304          // 48*48
#define BHN    24            // BATCH*NHEAD
#define MROWS  4608          // BATCH*NSEQ
#define SCALE  0.125f        // 64^-0.5

// ---------------- device scratch (static: no cudaMalloc allowed) ----------------
__device__ float g_q[BHN * NSEQ * HDIM];       // [bh][n][c], unscaled
__device__ float g_k[BHN * NSEQ * HDIM];
__device__ float g_v[BHN * NSEQ * HDIM];
__device__ float g_relh[BHN * NSEQ * GRID_H];  // [bh][q][kh]
__device__ float g_relw[BHN * NSEQ * GRID_H];  // [bh][q][kw]
__device__ float g_ao[MROWS * DIMM];           // attention output (b,n,dim)

// =================================================================
// SGEMM NT: C[M,N] = A[M,K] * B[N,K]^T (+bias). MODE 0: QKV epilogue
// scattering to g_q/g_k/g_v. MODE 1: A = g_ao, plain epilogue to Cout.
// =================================================================
#define BM 128
#define BN 128
#define BKG 16

template<int MODE>
__global__ __launch_bounds__(256) void sgemm_nt(const float* __restrict__ Aext,
                                                const float* __restrict__ B,
                                                const float* __restrict__ bias,
                                                float* __restrict__ Cout,
                                                int Ncol, int K)
{
    __shared__ float As[BKG][BM];
    __shared__ float Bs[BKG][BN];
    const float* A = (MODE == 0) ? Aext : (const float*)g_ao;

    const int m0 = blockIdx.y * BM;
    const int n0 = blockIdx.x * BN;
    const int tid = threadIdx.x;
    const int lr = tid >> 2;          // 0..63
    const int lc = (tid & 3) << 2;    // 0,4,8,12
    const int tr = tid >> 4;          // 0..15
    const int tc = tid & 15;          // 0..15

    float acc[8][8];
#pragma unroll
    for (int i = 0; i < 8; i++)
#pragma unroll
        for (int j = 0; j < 8; j++) acc[i][j] = 0.f;

    for (int k0 = 0; k0 < K; k0 += BKG) {
        float4 a0 = *(const float4*)(A + (size_t)(m0 + lr) * K + k0 + lc);
        float4 a1 = *(const float4*)(A + (size_t)(m0 + lr + 64) * K + k0 + lc);
        float4 b0 = *(const float4*)(B + (size_t)(n0 + lr) * K + k0 + lc);
        float4 b1 = *(const float4*)(B + (size_t)(n0 + lr + 64) * K + k0 + lc);
        __syncthreads();
        As[lc + 0][lr] = a0.x; As[lc + 1][lr] = a0.y; As[lc + 2][lr] = a0.z; As[lc + 3][lr] = a0.w;
        As[lc + 0][lr + 64] = a1.x; As[lc + 1][lr + 64] = a1.y; As[lc + 2][lr + 64] = a1.z; As[lc + 3][lr + 64] = a1.w;
        Bs[lc + 0][lr] = b0.x; Bs[lc + 1][lr] = b0.y; Bs[lc + 2][lr] = b0.z; Bs[lc + 3][lr] = b0.w;
        Bs[lc + 0][lr + 64] = b1.x; Bs[lc + 1][lr + 64] = b1.y; Bs[lc + 2][lr + 64] = b1.z; Bs[lc + 3][lr + 64] = b1.w;
        __syncthreads();
#pragma unroll
        for (int kk = 0; kk < BKG; kk++) {
            float af[8], bf[8];
            *(float4*)&af[0] = *(const float4*)&As[kk][tr * 8];
            *(float4*)&af[4] = *(const float4*)&As[kk][tr * 8 + 4];
            *(float4*)&bf[0] = *(const float4*)&Bs[kk][tc * 8];
            *(float4*)&bf[4] = *(const float4*)&Bs[kk][tc * 8 + 4];
#pragma unroll
            for (int i = 0; i < 8; i++)
#pragma unroll
                for (int j = 0; j < 8; j++) acc[i][j] += af[i] * bf[j];
        }
    }

    float bl[8];
    const int nb = n0 + tc * 8;
    *(float4*)&bl[0] = *(const float4*)(bias + nb);
    *(float4*)&bl[4] = *(const float4*)(bias + nb + 4);

    if (MODE == 0) {
        // scatter into q/k/v: col nb..nb+7 stays within one (part, head) since
        // 8 | 64 and tiles align to 128 | 768.
        const int p = nb / DIMM;
        const int hh = (nb % DIMM) / HDIM;
        const int cb = nb % HDIM;
        float* dst = (p == 0) ? g_q : ((p == 1) ? g_k : g_v);
#pragma unroll
        for (int i = 0; i < 8; i++) {
            int m = m0 + tr * 8 + i;
            int b = m / NSEQ, nn = m % NSEQ;
            float* drow = dst + (size_t)((b * NHEAD + hh) * NSEQ + nn) * HDIM + cb;
            float4 w0 = make_float4(acc[i][0] + bl[0], acc[i][1] + bl[1], acc[i][2] + bl[2], acc[i][3] + bl[3]);
            float4 w1 = make_float4(acc[i][4] + bl[4], acc[i][5] + bl[5], acc[i][6] + bl[6], acc[i][7] + bl[7]);
            *(float4*)(drow) = w0;
            *(float4*)(drow + 4) = w1;
        }
    } else {
#pragma unroll
        for (int i = 0; i < 8; i++) {
            int m = m0 + tr * 8 + i;
            float* drow = Cout + (size_t)m * Ncol + nb;
            float4 w0 = make_float4(acc[i][0] + bl[0], acc[i][1] + bl[1], acc[i][2] + bl[2], acc[i][3] + bl[3]);
            float4 w1 = make_float4(acc[i][4] + bl[4], acc[i][5] + bl[5], acc[i][6] + bl[6], acc[i][7] + bl[7]);
            *(float4*)(drow) = w0;
            *(float4*)(drow + 4) = w1;
        }
    }
}

// =================================================================
// rel bias tables: rel_h[bh][q][kh] = dot(q_vec, rel_pos_h[qh-kh+47])
//                  rel_w[bh][q][kw] = dot(q_vec, rel_pos_w[qw-kw+47])
// block = (qh, bh); loads q slice (48x64), 48 Rh rows, full Rw table.
// =================================================================
#define REL_SMEM ((3072 + 3072 + 6080) * 4)

__global__ __launch_bounds__(256) void rel_kernel(const float* __restrict__ rph,
                                                  const float* __restrict__ rpw)
{
    extern __shared__ float sm[];
    float* qs = sm;            // [48][64]
    float* rh = sm + 3072;     // [48][64]: rh[kh] = rph[qh-kh+47]
    float* rw = sm + 6144;     // [95][64]: full table

    const int qh = blockIdx.x;
    const int bh = blockIdx.y;
    const int tid = threadIdx.x;

    const float4* qsrc = (const float4*)(g_q + (size_t)(bh * NSEQ + qh * GRID_H) * HDIM);
#pragma unroll
    for (int i = 0; i < 3; i++) ((float4*)qs)[tid + i * 256] = qsrc[tid + i * 256];

    for (int i = tid; i < 768; i += 256) {
        int kh = i >> 4, cc = i & 15;
        ((float4*)rh)[i] = ((const float4*)(rph + (size_t)(qh - kh + 47) * HDIM))[cc];
    }
    for (int i = tid; i < 1520; i += 256) ((float4*)rw)[i] = ((const float4*)rpw)[i];
    __syncthreads();

    for (int idx = tid; idx < 2304; idx += 256) {
        int qw = idx / GRID_H;
        int kk = idx - qw * GRID_H;
        const float4* qp = (const float4*)(qs + qw * HDIM);
        const float4* hp = (const float4*)(rh + kk * HDIM);
        const float4* wp = (const float4*)(rw + (qw - kk + 47) * HDIM);
        float sh = 0.f, sw2 = 0.f;
#pragma unroll
        for (int c = 0; c < 16; c++) {
            float4 a = qp[c], hb = hp[c], wb = wp[c];
            sh  += a.x * hb.x + a.y * hb.y + a.z * hb.z + a.w * hb.w;
            sw2 += a.x * wb.x + a.y * wb.y + a.z * wb.z + a.w * wb.w;
        }
        size_t base = ((size_t)bh * NSEQ + (size_t)qh * GRID_H + qw) * GRID_H + kk;
        g_relh[base] = sh;
        g_relw[base] = sw2;
    }
}

// =================================================================
// Flash attention: 64-query x 64-key tiles, online softmax,
// bias = rel_h[q][kh] + rel_w[q][kw] from SMEM. 256 threads,
// 16x16 layout, 4x4 microtiles for both S=Q@K^T and O+=P@V.
// =================================================================
#define SK 68   // padded float stride (16B-aligned, conflict-reducing)
#define FLASH_SMEM ((4 * 64 * SK + 2 * 64 * GRID_H) * 4)

__global__ __launch_bounds__(256) void flash_kernel()
{
    extern __shared__ float sm[];
    float* Qt = sm;                 // [c][qr]  transposed
    float* Kt = Qt + 64 * SK;       // [c][kc]  transposed
    float* Vs = Kt + 64 * SK;       // [kc][c]  natural
    float* Pt = Vs + 64 * SK;       // [kc][qr] transposed P
    float* RH = Pt + 64 * SK;       // [qr][48]
    float* RW = RH + 64 * GRID_H;   // [qr][48]

    const int bh = blockIdx.y;
    const int q0 = blockIdx.x * 64;
    const int tid = threadIdx.x;
    const int ty = tid >> 4, tx = tid & 15;
    const int c0 = (tid & 15) * 4;
    const int rbase = tid >> 4;

    const float* qg = g_q + (size_t)bh * NSEQ * HDIM;
    const float* kg = g_k + (size_t)bh * NSEQ * HDIM;
    const float* vg = g_v + (size_t)bh * NSEQ * HDIM;

    // load Q tile transposed
#pragma unroll
    for (int it = 0; it < 4; it++) {
        int r = rbase + it * 16;
        float4 qv = *(const float4*)(qg + (size_t)(q0 + r) * HDIM + c0);
        Qt[(c0 + 0) * SK + r] = qv.x;
        Qt[(c0 + 1) * SK + r] = qv.y;
        Qt[(c0 + 2) * SK + r] = qv.z;
        Qt[(c0 + 3) * SK + r] = qv.w;
    }
    // load rel bias slices for this query tile (contiguous: [q][48])
    {
        const float4* srcH = (const float4*)(g_relh + ((size_t)bh * NSEQ + q0) * GRID_H);
        const float4* srcW = (const float4*)(g_relw + ((size_t)bh * NSEQ + q0) * GRID_H);
#pragma unroll
        for (int i = 0; i < 3; i++) {
            ((float4*)RH)[tid + i * 256] = srcH[tid + i * 256];
            ((float4*)RW)[tid + i * 256] = srcW[tid + i * 256];
        }
    }

    float o[4][4];
    float mrow[4], lrow[4];
#pragma unroll
    for (int i = 0; i < 4; i++) {
        mrow[i] = -1e30f; lrow[i] = 0.f;
#pragma unroll
        for (int j = 0; j < 4; j++) o[i][j] = 0.f;
    }

    for (int k0 = 0; k0 < NSEQ; k0 += 64) {
        __syncthreads();   // prev GEMM1/GEMM2 reads done; smem writable
#pragma unroll
        for (int it = 0; it < 4; it++) {
            int r = rbase + it * 16;
            float4 kv = *(const float4*)(kg + (size_t)(k0 + r) * HDIM + c0);
            Kt[(c0 + 0) * SK + r] = kv.x;
            Kt[(c0 + 1) * SK + r] = kv.y;
            Kt[(c0 + 2) * SK + r] = kv.z;
            Kt[(c0 + 3) * SK + r] = kv.w;
            float4 vv = *(const float4*)(vg + (size_t)(k0 + r) * HDIM + c0);
            *(float4*)(Vs + r * SK + c0) = vv;
        }
        __syncthreads();

        // S = Q @ K^T (4x4 per thread)
        float s[4][4];
#pragma unroll
        for (int i = 0; i < 4; i++)
#pragma unroll
            for (int j = 0; j < 4; j++) s[i][j] = 0.f;
#pragma unroll 16
        for (int c = 0; c < 64; c++) {
            float4 qa = *(const float4*)(Qt + c * SK + ty * 4);
            float4 kb = *(const float4*)(Kt + c * SK + tx * 4);
            float qa_[4] = {qa.x, qa.y, qa.z, qa.w};
            float kb_[4] = {kb.x, kb.y, kb.z, kb.w};
#pragma unroll
            for (int i = 0; i < 4; i++)
#pragma unroll
                for (int j = 0; j < 4; j++) s[i][j] += qa_[i] * kb_[j];
        }

        // scale + decomposed rel-pos bias
        int khj[4], kwj[4];
#pragma unroll
        for (int j = 0; j < 4; j++) {
            int kgl = k0 + tx * 4 + j;
            khj[j] = kgl / GRID_H;
            kwj[j] = kgl - khj[j] * GRID_H;
        }
#pragma unroll
        for (int i = 0; i < 4; i++) {
            int qr = ty * 4 + i;
            const float* rhq = RH + qr * GRID_H;
            const float* rwq = RW + qr * GRID_H;
#pragma unroll
            for (int j = 0; j < 4; j++)
                s[i][j] = s[i][j] * SCALE + rhq[khj[j]] + rwq[kwj[j]];
        }

        // online softmax: reduce over 16-lane groups (same ty)
        float tmax[4];
#pragma unroll
        for (int i = 0; i < 4; i++)
            tmax[i] = fmaxf(fmaxf(s[i][0], s[i][1]), fmaxf(s[i][2], s[i][3]));
#pragma unroll
        for (int off = 1; off < 16; off <<= 1)
#pragma unroll
            for (int i = 0; i < 4; i++)
                tmax[i] = fmaxf(tmax[i], __shfl_xor_sync(0xffffffffu, tmax[i], off));

        float corr[4], rsum[4];
#pragma unroll
        for (int i = 0; i < 4; i++) {
            float mn = fmaxf(mrow[i], tmax[i]);
            corr[i] = __expf(mrow[i] - mn);
            mrow[i] = mn;
            rsum[i] = 0.f;
        }
#pragma unroll
        for (int i = 0; i < 4; i++)
#pragma unroll
            for (int j = 0; j < 4; j++) {
                float p = __expf(s[i][j] - mrow[i]);
                s[i][j] = p;
                rsum[i] += p;
            }
#pragma unroll
        for (int off = 1; off < 16; off <<= 1)
#pragma unroll
            for (int i = 0; i < 4; i++)
                rsum[i] += __shfl_xor_sync(0xffffffffu, rsum[i], off);
#pragma unroll
        for (int i = 0; i < 4; i++) {
            lrow[i] = lrow[i] * corr[i] + rsum[i];
#pragma unroll
            for (int j = 0; j < 4; j++) o[i][j] *= corr[i];
        }

        // write P transposed: Pt[kc][qr]
#pragma unroll
        for (int j = 0; j < 4; j++) {
            float4 pv = make_float4(s[0][j], s[1][j], s[2][j], s[3][j]);
            *(float4*)(Pt + (tx * 4 + j) * SK + ty * 4) = pv;
        }
        __syncthreads();

        // O += P @ V
#pragma unroll 16
        for (int kk = 0; kk < 64; kk++) {
            float4 pa = *(const float4*)(Pt + kk * SK + ty * 4);
            float4 vb = *(const float4*)(Vs + kk * SK + tx * 4);
            float pa_[4] = {pa.x, pa.y, pa.z, pa.w};
            float vb_[4] = {vb.x, vb.y, vb.z, vb.w};
#pragma unroll
            for (int i = 0; i < 4; i++)
#pragma unroll
                for (int j = 0; j < 4; j++) o[i][j] += pa_[i] * vb_[j];
        }
    }

    // epilogue: normalize, write to (b, n, nh*64+c) layout
    const int b = bh / NHEAD, hh = bh % NHEAD;
#pragma unroll
    for (int i = 0; i < 4; i++) {
        int q = q0 + ty * 4 + i;
        float inv = 1.f / lrow[i];
        float4 ov = make_float4(o[i][0] * inv, o[i][1] * inv, o[i][2] * inv, o[i][3] * inv);
        *(float4*)(g_ao + (size_t)(b * NSEQ + q) * DIMM + hh * HDIM + tx * 4) = ov;
    }
}

// =================================================================
extern "C" void kernel_launch(void* const* d_in, const int* in_sizes, int n_in,
                              void* d_out, int out_size)
{
    const float* x     = (const float*)d_in[0];
    const float* rph   = (const float*)d_in[1];
    const float* rpw   = (const float*)d_in[2];
    const float* qkvw  = (const float*)d_in[3];
    const float* qkvb  = (const float*)d_in[4];
    const float* projw = (const float*)d_in[5];
    const float* projb = (const float*)d_in[6];
    float* out = (float*)d_out;

    cudaFuncSetAttribute(flash_kernel, cudaFuncAttributeMaxDynamicSharedMemorySize, FLASH_SMEM);
    cudaFuncSetAttribute(rel_kernel,   cudaFuncAttributeMaxDynamicSharedMemorySize, REL_SMEM);

    dim3 blk(256);
    // 1) QKV projection + head split
    sgemm_nt<0><<<dim3(2304 / BN, MROWS / BM), blk>>>(x, qkvw, qkvb, nullptr, 2304, DIMM);
    // 2) rel-pos bias tables
    rel_kernel<<<dim3(GRID_H, BHN), blk, REL_SMEM>>>(rph, rpw);
    // 3) fused flash attention with decomposed rel-pos bias
    flash_kernel<<<dim3(NSEQ / 64, BHN), blk, FLASH_SMEM>>>();
    // 4) output projection
    sgemm_nt<1><<<dim3(DIMM / BN, MROWS / BM), blk>>>(nullptr, projw, projb, out, DIMM, DIMM);
}

// round 3
// speedup vs baseline: 1.3221x; 1.3221x over previous
#include <cuda_runtime.h>
#include <math.h>
#include <stdint.h>

// Problem constants
#define DIMM   768
#define NHEAD  12
#define HDIM   64
#define BATCH  2
#define GRID_H 48
#define NSEQ   2304          // 48*48
#define BHN    24            // BATCH*NHEAD
#define MROWS  4608          // BATCH*NSEQ
#define SCALE  0.125f        // 64^-0.5

// ---------------- device scratch (static: no cudaMalloc allowed) ----------------
__device__ float g_q[BHN * NSEQ * HDIM];       // [bh][n][c], unscaled
__device__ float g_k[BHN * NSEQ * HDIM];
__device__ float g_v[BHN * NSEQ * HDIM];
__device__ float g_relh[BHN * NSEQ * GRID_H];  // [bh][q][kh]
__device__ float g_relw[BHN * NSEQ * GRID_H];  // [bh][q][kw]
__device__ float g_ao[MROWS * DIMM];           // attention output (b,n,dim)

// ---------------- tf32 helpers ----------------
__device__ __forceinline__ uint32_t f2tf32(float f) {
    uint32_t r;
    asm("cvt.rna.tf32.f32 %0, %1;" : "=r"(r) : "f"(f));
    return r;
}

// D(16x8,f32) += A(16x8,tf32,row) * B(8x8,tf32,col)
__device__ __forceinline__ void mma_tf32(float* d, const uint32_t* a,
                                         uint32_t b0, uint32_t b1) {
    asm volatile(
        "mma.sync.aligned.m16n8k8.row.col.f32.tf32.tf32.f32 "
        "{%0,%1,%2,%3}, {%4,%5,%6,%7}, {%8,%9}, {%0,%1,%2,%3};"
        : "+f"(d[0]), "+f"(d[1]), "+f"(d[2]), "+f"(d[3])
        : "r"(a[0]), "r"(a[1]), "r"(a[2]), "r"(a[3]), "r"(b0), "r"(b1));
}

// =================================================================
// SGEMM NT: C[M,N] = A[M,K] * B[N,K]^T (+bias). MODE 0: QKV epilogue
// scattering to g_q/g_k/g_v. MODE 1: A = g_ao, plain epilogue to Cout.
// =================================================================
#define BM 128
#define BN 128
#define BKG 16

template<int MODE>
__global__ __launch_bounds__(256) void sgemm_nt(const float* __restrict__ Aext,
                                                const float* __restrict__ B,
                                                const float* __restrict__ bias,
                                                float* __restrict__ Cout,
                                                int Ncol, int K)
{
    __shared__ float As[BKG][BM];
    __shared__ float Bs[BKG][BN];
    const float* A = (MODE == 0) ? Aext : (const float*)g_ao;

    const int m0 = blockIdx.y * BM;
    const int n0 = blockIdx.x * BN;
    const int tid = threadIdx.x;
    const int lr = tid >> 2;          // 0..63
    const int lc = (tid & 3) << 2;    // 0,4,8,12
    const int tr = tid >> 4;          // 0..15
    const int tc = tid & 15;          // 0..15

    float acc[8][8];
#pragma unroll
    for (int i = 0; i < 8; i++)
#pragma unroll
        for (int j = 0; j < 8; j++) acc[i][j] = 0.f;

    for (int k0 = 0; k0 < K; k0 += BKG) {
        float4 a0 = *(const float4*)(A + (size_t)(m0 + lr) * K + k0 + lc);
        float4 a1 = *(const float4*)(A + (size_t)(m0 + lr + 64) * K + k0 + lc);
        float4 b0 = *(const float4*)(B + (size_t)(n0 + lr) * K + k0 + lc);
        float4 b1 = *(const float4*)(B + (size_t)(n0 + lr + 64) * K + k0 + lc);
        __syncthreads();
        As[lc + 0][lr] = a0.x; As[lc + 1][lr] = a0.y; As[lc + 2][lr] = a0.z; As[lc + 3][lr] = a0.w;
        As[lc + 0][lr + 64] = a1.x; As[lc + 1][lr + 64] = a1.y; As[lc + 2][lr + 64] = a1.z; As[lc + 3][lr + 64] = a1.w;
        Bs[lc + 0][lr] = b0.x; Bs[lc + 1][lr] = b0.y; Bs[lc + 2][lr] = b0.z; Bs[lc + 3][lr] = b0.w;
        Bs[lc + 0][lr + 64] = b1.x; Bs[lc + 1][lr + 64] = b1.y; Bs[lc + 2][lr + 64] = b1.z; Bs[lc + 3][lr + 64] = b1.w;
        __syncthreads();
#pragma unroll
        for (int kk = 0; kk < BKG; kk++) {
            float af[8], bf[8];
            *(float4*)&af[0] = *(const float4*)&As[kk][tr * 8];
            *(float4*)&af[4] = *(const float4*)&As[kk][tr * 8 + 4];
            *(float4*)&bf[0] = *(const float4*)&Bs[kk][tc * 8];
            *(float4*)&bf[4] = *(const float4*)&Bs[kk][tc * 8 + 4];
#pragma unroll
            for (int i = 0; i < 8; i++)
#pragma unroll
                for (int j = 0; j < 8; j++) acc[i][j] += af[i] * bf[j];
        }
    }

    float bl[8];
    const int nb = n0 + tc * 8;
    *(float4*)&bl[0] = *(const float4*)(bias + nb);
    *(float4*)&bl[4] = *(const float4*)(bias + nb + 4);

    if (MODE == 0) {
        const int p = nb / DIMM;
        const int hh = (nb % DIMM) / HDIM;
        const int cb = nb % HDIM;
        float* dst = (p == 0) ? g_q : ((p == 1) ? g_k : g_v);
#pragma unroll
        for (int i = 0; i < 8; i++) {
            int m = m0 + tr * 8 + i;
            int b = m / NSEQ, nn = m % NSEQ;
            float* drow = dst + (size_t)((b * NHEAD + hh) * NSEQ + nn) * HDIM + cb;
            float4 w0 = make_float4(acc[i][0] + bl[0], acc[i][1] + bl[1], acc[i][2] + bl[2], acc[i][3] + bl[3]);
            float4 w1 = make_float4(acc[i][4] + bl[4], acc[i][5] + bl[5], acc[i][6] + bl[6], acc[i][7] + bl[7]);
            *(float4*)(drow) = w0;
            *(float4*)(drow + 4) = w1;
        }
    } else {
#pragma unroll
        for (int i = 0; i < 8; i++) {
            int m = m0 + tr * 8 + i;
            float* drow = Cout + (size_t)m * Ncol + nb;
            float4 w0 = make_float4(acc[i][0] + bl[0], acc[i][1] + bl[1], acc[i][2] + bl[2], acc[i][3] + bl[3]);
            float4 w1 = make_float4(acc[i][4] + bl[4], acc[i][5] + bl[5], acc[i][6] + bl[6], acc[i][7] + bl[7]);
            *(float4*)(drow) = w0;
            *(float4*)(drow + 4) = w1;
        }
    }
}

// =================================================================
// rel bias tables (unchanged)
// =================================================================
#define REL_SMEM ((3072 + 3072 + 6080) * 4)

__global__ __launch_bounds__(256) void rel_kernel(const float* __restrict__ rph,
                                                  const float* __restrict__ rpw)
{
    extern __shared__ float sm[];
    float* qs = sm;            // [48][64]
    float* rh = sm + 3072;     // [48][64]
    float* rw = sm + 6144;     // [95][64]

    const int qh = blockIdx.x;
    const int bh = blockIdx.y;
    const int tid = threadIdx.x;

    const float4* qsrc = (const float4*)(g_q + (size_t)(bh * NSEQ + qh * GRID_H) * HDIM);
#pragma unroll
    for (int i = 0; i < 3; i++) ((float4*)qs)[tid + i * 256] = qsrc[tid + i * 256];

    for (int i = tid; i < 768; i += 256) {
        int kh = i >> 4, cc = i & 15;
        ((float4*)rh)[i] = ((const float4*)(rph + (size_t)(qh - kh + 47) * HDIM))[cc];
    }
    for (int i = tid; i < 1520; i += 256) ((float4*)rw)[i] = ((const float4*)rpw)[i];
    __syncthreads();

    for (int idx = tid; idx < 2304; idx += 256) {
        int qw = idx / GRID_H;
        int kk = idx - qw * GRID_H;
        const float4* qp = (const float4*)(qs + qw * HDIM);
        const float4* hp = (const float4*)(rh + kk * HDIM);
        const float4* wp = (const float4*)(rw + (qw - kk + 47) * HDIM);
        float sh = 0.f, sw2 = 0.f;
#pragma unroll
        for (int c = 0; c < 16; c++) {
            float4 a = qp[c], hb = hp[c], wb = wp[c];
            sh  += a.x * hb.x + a.y * hb.y + a.z * hb.z + a.w * hb.w;
            sw2 += a.x * wb.x + a.y * wb.y + a.z * wb.z + a.w * wb.w;
        }
        size_t base = ((size_t)bh * NSEQ + (size_t)qh * GRID_H + qw) * GRID_H + kk;
        g_relh[base] = sh;
        g_relw[base] = sw2;
    }
}

// =================================================================
// Flash attention with tf32 tensor cores (mma.sync m16n8k8).
// 64-query tile, 4 warps (16 rows each), 64-key tiles, online softmax.
// =================================================================
#define KS_STRIDE 68   // ≡ 4 (mod 32): conflict-free A/B frag pattern
#define VS_STRIDE 72   // ≡ 8 (mod 32): conflict-free k-row B frag pattern
#define PS_STRIDE 68
#define RL_STRIDE 52   // ≡ 20 (mod 32)
#define FLASH_TC_SMEM ((64*KS_STRIDE + 64*VS_STRIDE + 64*PS_STRIDE + 2*64*RL_STRIDE) * 4)

__global__ __launch_bounds__(128) void flash_tc()
{
    extern __shared__ float sm[];
    float* Ks = sm;                     // [64][68] key-major, hd cols
    float* Vs = Ks + 64 * KS_STRIDE;    // [64][72] key-major, hd cols
    float* Ps = Vs + 64 * VS_STRIDE;    // [64][68] q-major, key cols
    float* RH = Ps + 64 * PS_STRIDE;    // [64][52]
    float* RW = RH + 64 * RL_STRIDE;    // [64][52]

    const int bh = blockIdx.y;
    const int q0 = blockIdx.x * 64;
    const int tid = threadIdx.x;
    const int lane = tid & 31;
    const int wid = tid >> 5;
    const int wrow = wid * 16;          // warp's q-row stripe base (tile-local)
    const int gr = lane >> 2;           // 0..7
    const int gc = lane & 3;            // 0..3

    const float* qg = g_q + (size_t)bh * NSEQ * HDIM;
    const float* kg = g_k + (size_t)bh * NSEQ * HDIM;
    const float* vg = g_v + (size_t)bh * NSEQ * HDIM;

    // ---- Q fragments: scaled, tf32-rounded, kept in registers for all iters
    uint32_t qa[8][4];
    {
        const float* qr0 = qg + (size_t)(q0 + wrow + gr) * HDIM;
        const float* qr1 = qr0 + 8 * HDIM;
#pragma unroll
        for (int ks = 0; ks < 8; ks++) {
            qa[ks][0] = f2tf32(qr0[ks * 8 + gc] * SCALE);
            qa[ks][1] = f2tf32(qr1[ks * 8 + gc] * SCALE);
            qa[ks][2] = f2tf32(qr0[ks * 8 + gc + 4] * SCALE);
            qa[ks][3] = f2tf32(qr1[ks * 8 + gc + 4] * SCALE);
        }
    }

    // ---- rel bias slices into SMEM: [64][48] padded to stride 52
    {
        const float4* srcH = (const float4*)(g_relh + ((size_t)bh * NSEQ + q0) * GRID_H);
        const float4* srcW = (const float4*)(g_relw + ((size_t)bh * NSEQ + q0) * GRID_H);
        for (int i = tid; i < 768; i += 128) {   // 64 rows * 12 float4/row
            int r = i / 12, c4 = i % 12;
            ((float4*)RH)[r * (RL_STRIDE / 4) + c4] = srcH[i];
            ((float4*)RW)[r * (RL_STRIDE / 4) + c4] = srcW[i];
        }
    }

    float o[8][4];
    float m0r = -1e30f, m1r = -1e30f, l0r = 0.f, l1r = 0.f;
#pragma unroll
    for (int nt = 0; nt < 8; nt++)
#pragma unroll
        for (int j = 0; j < 4; j++) o[nt][j] = 0.f;

    const int ldrow = tid >> 1;          // 0..63 (K/V staging row)
    const int ldc0 = (tid & 1) * 32;     // column half

    for (int k0 = 0; k0 < NSEQ; k0 += 64) {
        __syncthreads();
        // ---- stage K/V tiles (tf32-rounded)
        {
            const float* krow = kg + (size_t)(k0 + ldrow) * HDIM + ldc0;
            const float* vrow = vg + (size_t)(k0 + ldrow) * HDIM + ldc0;
            float* kd = Ks + ldrow * KS_STRIDE + ldc0;
            float* vd = Vs + ldrow * VS_STRIDE + ldc0;
#pragma unroll
            for (int i = 0; i < 8; i++) {
                float4 kv = *(const float4*)(krow + i * 4);
                float4 vv = *(const float4*)(vrow + i * 4);
                kv.x = __uint_as_float(f2tf32(kv.x)); kv.y = __uint_as_float(f2tf32(kv.y));
                kv.z = __uint_as_float(f2tf32(kv.z)); kv.w = __uint_as_float(f2tf32(kv.w));
                vv.x = __uint_as_float(f2tf32(vv.x)); vv.y = __uint_as_float(f2tf32(vv.y));
                vv.z = __uint_as_float(f2tf32(vv.z)); vv.w = __uint_as_float(f2tf32(vv.w));
                *(float4*)(kd + i * 4) = kv;
                *(float4*)(vd + i * 4) = vv;
            }
        }
        __syncthreads();

        // ---- S = Q @ K^T : s[nt] covers key cols nt*8..nt*8+7
        float s[8][4];
#pragma unroll
        for (int nt = 0; nt < 8; nt++) {
            s[nt][0] = s[nt][1] = s[nt][2] = s[nt][3] = 0.f;
            const uint32_t* kb = (const uint32_t*)(Ks + (nt * 8 + gr) * KS_STRIDE);
#pragma unroll
            for (int ks = 0; ks < 8; ks++) {
                uint32_t b0 = kb[ks * 8 + gc];
                uint32_t b1 = kb[ks * 8 + gc + 4];
                mma_tf32(s[nt], qa[ks], b0, b1);
            }
        }

        // ---- add decomposed rel-pos bias
        {
            const float* rh0 = RH + (wrow + gr) * RL_STRIDE;
            const float* rw0 = RW + (wrow + gr) * RL_STRIDE;
            const float* rh1 = rh0 + 8 * RL_STRIDE;
            const float* rw1 = rw0 + 8 * RL_STRIDE;
#pragma unroll
            for (int nt = 0; nt < 8; nt++) {
                int c0 = k0 + nt * 8 + 2 * gc;
                int kh0 = c0 / GRID_H, kw0 = c0 - kh0 * GRID_H;
                int c1 = c0 + 1;
                int kh1 = c1 / GRID_H, kw1 = c1 - kh1 * GRID_H;
                s[nt][0] += rh0[kh0] + rw0[kw0];
                s[nt][1] += rh0[kh1] + rw0[kw1];
                s[nt][2] += rh1[kh0] + rw1[kw0];
                s[nt][3] += rh1[kh1] + rw1[kw1];
            }
        }

        // ---- online softmax over this 64-key tile (rows wrow+gr, wrow+gr+8)
        float t0 = -1e30f, t1 = -1e30f;
#pragma unroll
        for (int nt = 0; nt < 8; nt++) {
            t0 = fmaxf(t0, fmaxf(s[nt][0], s[nt][1]));
            t1 = fmaxf(t1, fmaxf(s[nt][2], s[nt][3]));
        }
        t0 = fmaxf(t0, __shfl_xor_sync(0xffffffffu, t0, 1));
        t0 = fmaxf(t0, __shfl_xor_sync(0xffffffffu, t0, 2));
        t1 = fmaxf(t1, __shfl_xor_sync(0xffffffffu, t1, 1));
        t1 = fmaxf(t1, __shfl_xor_sync(0xffffffffu, t1, 2));

        float mn0 = fmaxf(m0r, t0), mn1 = fmaxf(m1r, t1);
        float c0f = __expf(m0r - mn0), c1f = __expf(m1r - mn1);
        m0r = mn0; m1r = mn1;

        float rs0 = 0.f, rs1 = 0.f;
        float* pr0 = Ps + (wrow + gr) * PS_STRIDE + 2 * gc;
        float* pr1 = pr0 + 8 * PS_STRIDE;
#pragma unroll
        for (int nt = 0; nt < 8; nt++) {
            float p0 = __expf(s[nt][0] - mn0);
            float p1 = __expf(s[nt][1] - mn0);
            float p2 = __expf(s[nt][2] - mn1);
            float p3 = __expf(s[nt][3] - mn1);
            rs0 += p0 + p1;
            rs1 += p2 + p3;
            *(float2*)(pr0 + nt * 8) = make_float2(__uint_as_float(f2tf32(p0)), __uint_as_float(f2tf32(p1)));
            *(float2*)(pr1 + nt * 8) = make_float2(__uint_as_float(f2tf32(p2)), __uint_as_float(f2tf32(p3)));
        }
        rs0 += __shfl_xor_sync(0xffffffffu, rs0, 1);
        rs0 += __shfl_xor_sync(0xffffffffu, rs0, 2);
        rs1 += __shfl_xor_sync(0xffffffffu, rs1, 1);
        rs1 += __shfl_xor_sync(0xffffffffu, rs1, 2);
        l0r = l0r * c0f + rs0;
        l1r = l1r * c1f + rs1;
#pragma unroll
        for (int nt = 0; nt < 8; nt++) {
            o[nt][0] *= c0f; o[nt][1] *= c0f;
            o[nt][2] *= c1f; o[nt][3] *= c1f;
        }
        __syncwarp();

        // ---- O += P @ V  (A = P from Ps, B = V from Vs)
        const uint32_t* pb0 = (const uint32_t*)(Ps + (wrow + gr) * PS_STRIDE);
        const uint32_t* pb1 = (const uint32_t*)(Ps + (wrow + gr + 8) * PS_STRIDE);
#pragma unroll
        for (int ks = 0; ks < 8; ks++) {
            uint32_t pa[4];
            pa[0] = pb0[ks * 8 + gc];
            pa[1] = pb1[ks * 8 + gc];
            pa[2] = pb0[ks * 8 + gc + 4];
            pa[3] = pb1[ks * 8 + gc + 4];
            const uint32_t* vb0 = (const uint32_t*)(Vs + (ks * 8 + gc) * VS_STRIDE);
            const uint32_t* vb1 = (const uint32_t*)(Vs + (ks * 8 + gc + 4) * VS_STRIDE);
#pragma unroll
            for (int nt = 0; nt < 8; nt++) {
                mma_tf32(o[nt], pa, vb0[nt * 8 + gr], vb1[nt * 8 + gr]);
            }
        }
    }

    // ---- epilogue: normalize, write to g_ao (b, n, nh*64+c)
    const int b = bh / NHEAD, hh = bh % NHEAD;
    const float inv0 = 1.f / l0r, inv1 = 1.f / l1r;
    float* d0 = g_ao + (size_t)(b * NSEQ + q0 + wrow + gr) * DIMM + hh * HDIM + 2 * gc;
    float* d1 = d0 + (size_t)8 * DIMM;
#pragma unroll
    for (int nt = 0; nt < 8; nt++) {
        *(float2*)(d0 + nt * 8) = make_float2(o[nt][0] * inv0, o[nt][1] * inv0);
        *(float2*)(d1 + nt * 8) = make_float2(o[nt][2] * inv1, o[nt][3] * inv1);
    }
}

// =================================================================
extern "C" void kernel_launch(void* const* d_in, const int* in_sizes, int n_in,
                              void* d_out, int out_size)
{
    const float* x     = (const float*)d_in[0];
    const float* rph   = (const float*)d_in[1];
    const float* rpw   = (const float*)d_in[2];
    const float* qkvw  = (const float*)d_in[3];
    const float* qkvb  = (const float*)d_in[4];
    const float* projw = (const float*)d_in[5];
    const float* projb = (const float*)d_in[6];
    float* out = (float*)d_out;

    cudaFuncSetAttribute(flash_tc,   cudaFuncAttributeMaxDynamicSharedMemorySize, FLASH_TC_SMEM);
    cudaFuncSetAttribute(rel_kernel, cudaFuncAttributeMaxDynamicSharedMemorySize, REL_SMEM);

    // 1) QKV projection + head split
    sgemm_nt<0><<<dim3(2304 / BN, MROWS / BM), dim3(256)>>>(x, qkvw, qkvb, nullptr, 2304, DIMM);
    // 2) rel-pos bias tables
    rel_kernel<<<dim3(GRID_H, BHN), dim3(256), REL_SMEM>>>(rph, rpw);
    // 3) fused flash attention (tf32 tensor cores)
    flash_tc<<<dim3(NSEQ / 64, BHN), dim3(128), FLASH_TC_SMEM>>>();
    // 4) output projection
    sgemm_nt<1><<<dim3(DIMM / BN, MROWS / BM), dim3(256)>>>(nullptr, projw, projb, out, DIMM, DIMM);
}

// round 4
// speedup vs baseline: 2.1410x; 1.6194x over previous
#include <cuda_runtime.h>
#include <math.h>
#include <stdint.h>

// Problem constants
#define DIMM   768
#define NHEAD  12
#define HDIM   64
#define BATCH  2
#define GRID_H 48
#define NSEQ   2304          // 48*48
#define BHN    24            // BATCH*NHEAD
#define MROWS  4608          // BATCH*NSEQ
#define SCALE  0.125f        // 64^-0.5

// ---------------- device scratch (static: no cudaMalloc allowed) ----------------
__device__ float g_q[BHN * NSEQ * HDIM];       // [bh][n][c], unscaled
__device__ float g_k[BHN * NSEQ * HDIM];
__device__ float g_v[BHN * NSEQ * HDIM];
__device__ float g_relh[BHN * NSEQ * GRID_H];  // [bh][q][kh]
__device__ float g_relw[BHN * NSEQ * GRID_H];  // [bh][q][kw]
__device__ float g_ao[MROWS * DIMM];           // attention output (b,n,dim)

// ---------------- tf32 helpers ----------------
__device__ __forceinline__ uint32_t f2tf32(float f) {
    uint32_t r;
    asm("cvt.rna.tf32.f32 %0, %1;" : "=r"(r) : "f"(f));
    return r;
}
__device__ __forceinline__ float tf32f(float f) { return __uint_as_float(f2tf32(f)); }

// D(16x8,f32) += A(16x8,tf32,row) * B(8x8,tf32,col)
__device__ __forceinline__ void mma_tf32(float* d, const uint32_t* a,
                                         uint32_t b0, uint32_t b1) {
    asm volatile(
        "mma.sync.aligned.m16n8k8.row.col.f32.tf32.tf32.f32 "
        "{%0,%1,%2,%3}, {%4,%5,%6,%7}, {%8,%9}, {%0,%1,%2,%3};"
        : "+f"(d[0]), "+f"(d[1]), "+f"(d[2]), "+f"(d[3])
        : "r"(a[0]), "r"(a[1]), "r"(a[2]), "r"(a[3]), "r"(b0), "r"(b1));
}

// =================================================================
// tf32 tensor-core GEMM NT: C[M,N] = A[M,K] * B[N,K]^T (+bias).
// 128x128x16 tiles, 8 warps (2m x 4n), warp tile 64x32, m16n8k8.
// MODE 0: QKV epilogue scattering to g_q/g_k/g_v. MODE 1: A = g_ao,
// plain epilogue to Cout.
// =================================================================
#define GPAD 20

template<int MODE>
__global__ __launch_bounds__(256) void gemm_tc(const float* __restrict__ Aext,
                                               const float* __restrict__ B,
                                               const float* __restrict__ bias,
                                               float* __restrict__ Cout,
                                               int Ncol, int K)
{
    __shared__ float As[128][GPAD];
    __shared__ float Bs[128][GPAD];
    const float* A = (MODE == 0) ? Aext : (const float*)g_ao;

    const int m0 = blockIdx.y * 128;
    const int n0 = blockIdx.x * 128;
    const int tid = threadIdx.x;
    const int lane = tid & 31;
    const int wid = tid >> 5;
    const int wm = (wid & 1) * 64;   // warp m-offset
    const int wn = (wid >> 1) * 32;  // warp n-offset
    const int gr = lane >> 2;        // 0..7
    const int gc = lane & 3;         // 0..3
    const int sr = tid >> 2;         // staging row 0..63
    const int sc = (tid & 3) << 2;   // staging col 0,4,8,12

    float acc[4][4][4];
#pragma unroll
    for (int mi = 0; mi < 4; mi++)
#pragma unroll
        for (int ni = 0; ni < 4; ni++)
#pragma unroll
            for (int j = 0; j < 4; j++) acc[mi][ni][j] = 0.f;

    for (int k0 = 0; k0 < K; k0 += 16) {
        float4 av0 = *(const float4*)(A + (size_t)(m0 + sr) * K + k0 + sc);
        float4 av1 = *(const float4*)(A + (size_t)(m0 + sr + 64) * K + k0 + sc);
        float4 bv0 = *(const float4*)(B + (size_t)(n0 + sr) * K + k0 + sc);
        float4 bv1 = *(const float4*)(B + (size_t)(n0 + sr + 64) * K + k0 + sc);
        __syncthreads();
        As[sr][sc + 0] = tf32f(av0.x); As[sr][sc + 1] = tf32f(av0.y);
        As[sr][sc + 2] = tf32f(av0.z); As[sr][sc + 3] = tf32f(av0.w);
        As[sr + 64][sc + 0] = tf32f(av1.x); As[sr + 64][sc + 1] = tf32f(av1.y);
        As[sr + 64][sc + 2] = tf32f(av1.z); As[sr + 64][sc + 3] = tf32f(av1.w);
        Bs[sr][sc + 0] = tf32f(bv0.x); Bs[sr][sc + 1] = tf32f(bv0.y);
        Bs[sr][sc + 2] = tf32f(bv0.z); Bs[sr][sc + 3] = tf32f(bv0.w);
        Bs[sr + 64][sc + 0] = tf32f(bv1.x); Bs[sr + 64][sc + 1] = tf32f(bv1.y);
        Bs[sr + 64][sc + 2] = tf32f(bv1.z); Bs[sr + 64][sc + 3] = tf32f(bv1.w);
        __syncthreads();

#pragma unroll
        for (int kk = 0; kk < 16; kk += 8) {
            uint32_t af[4][4], bf[4][2];
#pragma unroll
            for (int mi = 0; mi < 4; mi++) {
                const float* ap = &As[wm + mi * 16 + gr][kk + gc];
                af[mi][0] = __float_as_uint(ap[0]);
                af[mi][1] = __float_as_uint(ap[8 * GPAD]);
                af[mi][2] = __float_as_uint(ap[4]);
                af[mi][3] = __float_as_uint(ap[8 * GPAD + 4]);
            }
#pragma unroll
            for (int ni = 0; ni < 4; ni++) {
                const float* bp = &Bs[wn + ni * 8 + gr][kk + gc];
                bf[ni][0] = __float_as_uint(bp[0]);
                bf[ni][1] = __float_as_uint(bp[4]);
            }
#pragma unroll
            for (int mi = 0; mi < 4; mi++)
#pragma unroll
                for (int ni = 0; ni < 4; ni++)
                    mma_tf32(acc[mi][ni], af[mi], bf[ni][0], bf[ni][1]);
        }
    }

    // ---- epilogue
#pragma unroll
    for (int ni = 0; ni < 4; ni++) {
        const int nb = n0 + wn + ni * 8 + 2 * gc;
        const float bbx = bias[nb], bby = bias[nb + 1];
        if (MODE == 0) {
            const int p = nb / DIMM;
            const int hh = (nb % DIMM) / HDIM;
            const int cb = nb % HDIM;
            float* dst = (p == 0) ? g_q : ((p == 1) ? g_k : g_v);
#pragma unroll
            for (int mi = 0; mi < 4; mi++) {
                int m = m0 + wm + mi * 16 + gr;
                int b = m / NSEQ, nn = m % NSEQ;
                float* d0 = dst + (size_t)((b * NHEAD + hh) * NSEQ + nn) * HDIM + cb;
                *(float2*)d0 = make_float2(acc[mi][ni][0] + bbx, acc[mi][ni][1] + bby);
                int m2 = m + 8;
                int b2 = m2 / NSEQ, nn2 = m2 % NSEQ;
                float* d1 = dst + (size_t)((b2 * NHEAD + hh) * NSEQ + nn2) * HDIM + cb;
                *(float2*)d1 = make_float2(acc[mi][ni][2] + bbx, acc[mi][ni][3] + bby);
            }
        } else {
#pragma unroll
            for (int mi = 0; mi < 4; mi++) {
                int m = m0 + wm + mi * 16 + gr;
                *(float2*)(Cout + (size_t)m * Ncol + nb) =
                    make_float2(acc[mi][ni][0] + bbx, acc[mi][ni][1] + bby);
                *(float2*)(Cout + (size_t)(m + 8) * Ncol + nb) =
                    make_float2(acc[mi][ni][2] + bbx, acc[mi][ni][3] + bby);
            }
        }
    }
}

// =================================================================
// rel bias tables (unchanged)
// =================================================================
#define REL_SMEM ((3072 + 3072 + 6080) * 4)

__global__ __launch_bounds__(256) void rel_kernel(const float* __restrict__ rph,
                                                  const float* __restrict__ rpw)
{
    extern __shared__ float sm[];
    float* qs = sm;            // [48][64]
    float* rh = sm + 3072;     // [48][64]
    float* rw = sm + 6144;     // [95][64]

    const int qh = blockIdx.x;
    const int bh = blockIdx.y;
    const int tid = threadIdx.x;

    const float4* qsrc = (const float4*)(g_q + (size_t)(bh * NSEQ + qh * GRID_H) * HDIM);
#pragma unroll
    for (int i = 0; i < 3; i++) ((float4*)qs)[tid + i * 256] = qsrc[tid + i * 256];

    for (int i = tid; i < 768; i += 256) {
        int kh = i >> 4, cc = i & 15;
        ((float4*)rh)[i] = ((const float4*)(rph + (size_t)(qh - kh + 47) * HDIM))[cc];
    }
    for (int i = tid; i < 1520; i += 256) ((float4*)rw)[i] = ((const float4*)rpw)[i];
    __syncthreads();

    for (int idx = tid; idx < 2304; idx += 256) {
        int qw = idx / GRID_H;
        int kk = idx - qw * GRID_H;
        const float4* qp = (const float4*)(qs + qw * HDIM);
        const float4* hp = (const float4*)(rh + kk * HDIM);
        const float4* wp = (const float4*)(rw + (qw - kk + 47) * HDIM);
        float sh = 0.f, sw2 = 0.f;
#pragma unroll
        for (int c = 0; c < 16; c++) {
            float4 a = qp[c], hb = hp[c], wb = wp[c];
            sh  += a.x * hb.x + a.y * hb.y + a.z * hb.z + a.w * hb.w;
            sw2 += a.x * wb.x + a.y * wb.y + a.z * wb.z + a.w * wb.w;
        }
        size_t base = ((size_t)bh * NSEQ + (size_t)qh * GRID_H + qw) * GRID_H + kk;
        g_relh[base] = sh;
        g_relw[base] = sw2;
    }
}

// =================================================================
// Flash attention with tf32 tensor cores (mma.sync m16n8k8).
// 128-query tile, 8 warps (16 rows each), 64-key tiles, online softmax,
// register-prefetched K/V staging.
// =================================================================
#define KS_STRIDE 68   // ≡ 4 (mod 32)
#define VS_STRIDE 72   // ≡ 8 (mod 32)
#define PS_STRIDE 68
#define RL_STRIDE 52   // ≡ 20 (mod 32)
#define FLASH_TC_SMEM ((64*KS_STRIDE + 64*VS_STRIDE + 128*PS_STRIDE + 2*128*RL_STRIDE) * 4)

__global__ __launch_bounds__(256) void flash_tc()
{
    extern __shared__ float sm[];
    float* Ks = sm;                     // [64][68]  key-major, hd cols
    float* Vs = Ks + 64 * KS_STRIDE;    // [64][72]  key-major, hd cols
    float* Ps = Vs + 64 * VS_STRIDE;    // [128][68] q-major, key cols
    float* RH = Ps + 128 * PS_STRIDE;   // [128][52]
    float* RW = RH + 128 * RL_STRIDE;   // [128][52]

    const int bh = blockIdx.y;
    const int q0 = blockIdx.x * 128;
    const int tid = threadIdx.x;
    const int lane = tid & 31;
    const int wid = tid >> 5;
    const int wrow = wid * 16;          // warp's q-row stripe base (tile-local)
    const int gr = lane >> 2;           // 0..7
    const int gc = lane & 3;            // 0..3

    const float* qg = g_q + (size_t)bh * NSEQ * HDIM;
    const float* kg = g_k + (size_t)bh * NSEQ * HDIM;
    const float* vg = g_v + (size_t)bh * NSEQ * HDIM;

    // ---- Q fragments: scaled, tf32-rounded, kept in registers for all iters
    uint32_t qa[8][4];
    {
        const float* qr0 = qg + (size_t)(q0 + wrow + gr) * HDIM;
        const float* qr1 = qr0 + 8 * HDIM;
#pragma unroll
        for (int ks = 0; ks < 8; ks++) {
            qa[ks][0] = f2tf32(qr0[ks * 8 + gc] * SCALE);
            qa[ks][1] = f2tf32(qr1[ks * 8 + gc] * SCALE);
            qa[ks][2] = f2tf32(qr0[ks * 8 + gc + 4] * SCALE);
            qa[ks][3] = f2tf32(qr1[ks * 8 + gc + 4] * SCALE);
        }
    }

    // ---- rel bias slices into SMEM: [128][48] padded to stride 52
    {
        const float4* srcH = (const float4*)(g_relh + ((size_t)bh * NSEQ + q0) * GRID_H);
        const float4* srcW = (const float4*)(g_relw + ((size_t)bh * NSEQ + q0) * GRID_H);
        for (int i = tid; i < 1536; i += 256) {   // 128 rows * 12 float4/row
            int r = i / 12, c4 = i % 12;
            ((float4*)RH)[r * (RL_STRIDE / 4) + c4] = srcH[i];
            ((float4*)RW)[r * (RL_STRIDE / 4) + c4] = srcW[i];
        }
    }

    float o[8][4];
    float m0r = -1e30f, m1r = -1e30f, l0r = 0.f, l1r = 0.f;
#pragma unroll
    for (int nt = 0; nt < 8; nt++)
#pragma unroll
        for (int j = 0; j < 4; j++) o[nt][j] = 0.f;

    const int ldrow = tid >> 2;          // 0..63 (K/V staging row)
    const int ldc0 = (tid & 3) * 16;     // 16-col slice

    // prefetch tile 0 into registers
    float4 kpre[4], vpre[4];
#pragma unroll
    for (int i = 0; i < 4; i++) {
        kpre[i] = *(const float4*)(kg + (size_t)ldrow * HDIM + ldc0 + i * 4);
        vpre[i] = *(const float4*)(vg + (size_t)ldrow * HDIM + ldc0 + i * 4);
    }

    for (int k0 = 0; k0 < NSEQ; k0 += 64) {
        __syncthreads();
        // ---- store prefetched K/V tile (tf32-rounded)
        {
            float* kd = Ks + ldrow * KS_STRIDE + ldc0;
            float* vd = Vs + ldrow * VS_STRIDE + ldc0;
#pragma unroll
            for (int i = 0; i < 4; i++) {
                *(float4*)(kd + i * 4) = make_float4(tf32f(kpre[i].x), tf32f(kpre[i].y),
                                                     tf32f(kpre[i].z), tf32f(kpre[i].w));
                *(float4*)(vd + i * 4) = make_float4(tf32f(vpre[i].x), tf32f(vpre[i].y),
                                                     tf32f(vpre[i].z), tf32f(vpre[i].w));
            }
        }
        // ---- prefetch next tile (overlaps with compute below)
        if (k0 + 64 < NSEQ) {
            const float* krow = kg + (size_t)(k0 + 64 + ldrow) * HDIM + ldc0;
            const float* vrow = vg + (size_t)(k0 + 64 + ldrow) * HDIM + ldc0;
#pragma unroll
            for (int i = 0; i < 4; i++) {
                kpre[i] = *(const float4*)(krow + i * 4);
                vpre[i] = *(const float4*)(vrow + i * 4);
            }
        }
        __syncthreads();

        // ---- S = Q @ K^T : s[nt] covers key cols nt*8..nt*8+7
        float s[8][4];
#pragma unroll
        for (int nt = 0; nt < 8; nt++) {
            s[nt][0] = s[nt][1] = s[nt][2] = s[nt][3] = 0.f;
            const uint32_t* kb = (const uint32_t*)(Ks + (nt * 8 + gr) * KS_STRIDE);
#pragma unroll
            for (int ks = 0; ks < 8; ks++) {
                uint32_t b0 = kb[ks * 8 + gc];
                uint32_t b1 = kb[ks * 8 + gc + 4];
                mma_tf32(s[nt], qa[ks], b0, b1);
            }
        }

        // ---- add decomposed rel-pos bias
        {
            const float* rh0 = RH + (wrow + gr) * RL_STRIDE;
            const float* rw0 = RW + (wrow + gr) * RL_STRIDE;
            const float* rh1 = rh0 + 8 * RL_STRIDE;
            const float* rw1 = rw0 + 8 * RL_STRIDE;
#pragma unroll
            for (int nt = 0; nt < 8; nt++) {
                int c0 = k0 + nt * 8 + 2 * gc;
                int kh0 = c0 / GRID_H, kw0 = c0 - kh0 * GRID_H;
                int c1 = c0 + 1;
                int kh1 = c1 / GRID_H, kw1 = c1 - kh1 * GRID_H;
                s[nt][0] += rh0[kh0] + rw0[kw0];
                s[nt][1] += rh0[kh1] + rw0[kw1];
                s[nt][2] += rh1[kh0] + rw1[kw0];
                s[nt][3] += rh1[kh1] + rw1[kw1];
            }
        }

        // ---- online softmax over this 64-key tile
        float t0 = -1e30f, t1 = -1e30f;
#pragma unroll
        for (int nt = 0; nt < 8; nt++) {
            t0 = fmaxf(t0, fmaxf(s[nt][0], s[nt][1]));
            t1 = fmaxf(t1, fmaxf(s[nt][2], s[nt][3]));
        }
        t0 = fmaxf(t0, __shfl_xor_sync(0xffffffffu, t0, 1));
        t0 = fmaxf(t0, __shfl_xor_sync(0xffffffffu, t0, 2));
        t1 = fmaxf(t1, __shfl_xor_sync(0xffffffffu, t1, 1));
        t1 = fmaxf(t1, __shfl_xor_sync(0xffffffffu, t1, 2));

        float mn0 = fmaxf(m0r, t0), mn1 = fmaxf(m1r, t1);
        float c0f = __expf(m0r - mn0), c1f = __expf(m1r - mn1);
        m0r = mn0; m1r = mn1;

        float rs0 = 0.f, rs1 = 0.f;
        float* pr0 = Ps + (wrow + gr) * PS_STRIDE + 2 * gc;
        float* pr1 = pr0 + 8 * PS_STRIDE;
#pragma unroll
        for (int nt = 0; nt < 8; nt++) {
            float p0 = __expf(s[nt][0] - mn0);
            float p1 = __expf(s[nt][1] - mn0);
            float p2 = __expf(s[nt][2] - mn1);
            float p3 = __expf(s[nt][3] - mn1);
            rs0 += p0 + p1;
            rs1 += p2 + p3;
            *(float2*)(pr0 + nt * 8) = make_float2(__uint_as_float(f2tf32(p0)), __uint_as_float(f2tf32(p1)));
            *(float2*)(pr1 + nt * 8) = make_float2(__uint_as_float(f2tf32(p2)), __uint_as_float(f2tf32(p3)));
        }
        rs0 += __shfl_xor_sync(0xffffffffu, rs0, 1);
        rs0 += __shfl_xor_sync(0xffffffffu, rs0, 2);
        rs1 += __shfl_xor_sync(0xffffffffu, rs1, 1);
        rs1 += __shfl_xor_sync(0xffffffffu, rs1, 2);
        l0r = l0r * c0f + rs0;
        l1r = l1r * c1f + rs1;
#pragma unroll
        for (int nt = 0; nt < 8; nt++) {
            o[nt][0] *= c0f; o[nt][1] *= c0f;
            o[nt][2] *= c1f; o[nt][3] *= c1f;
        }
        __syncwarp();

        // ---- O += P @ V  (A = P from Ps, B = V from Vs)
        const uint32_t* pb0 = (const uint32_t*)(Ps + (wrow + gr) * PS_STRIDE);
        const uint32_t* pb1 = (const uint32_t*)(Ps + (wrow + gr + 8) * PS_STRIDE);
#pragma unroll
        for (int ks = 0; ks < 8; ks++) {
            uint32_t pa[4];
            pa[0] = pb0[ks * 8 + gc];
            pa[1] = pb1[ks * 8 + gc];
            pa[2] = pb0[ks * 8 + gc + 4];
            pa[3] = pb1[ks * 8 + gc + 4];
            const uint32_t* vb0 = (const uint32_t*)(Vs + (ks * 8 + gc) * VS_STRIDE);
            const uint32_t* vb1 = (const uint32_t*)(Vs + (ks * 8 + gc + 4) * VS_STRIDE);
#pragma unroll
            for (int nt = 0; nt < 8; nt++) {
                mma_tf32(o[nt], pa, vb0[nt * 8 + gr], vb1[nt * 8 + gr]);
            }
        }
    }

    // ---- epilogue: normalize, write to g_ao (b, n, nh*64+c)
    const int b = bh / NHEAD, hh = bh % NHEAD;
    const float inv0 = 1.f / l0r, inv1 = 1.f / l1r;
    float* d0 = g_ao + (size_t)(b * NSEQ + q0 + wrow + gr) * DIMM + hh * HDIM + 2 * gc;
    float* d1 = d0 + (size_t)8 * DIMM;
#pragma unroll
    for (int nt = 0; nt < 8; nt++) {
        *(float2*)(d0 + nt * 8) = make_float2(o[nt][0] * inv0, o[nt][1] * inv0);
        *(float2*)(d1 + nt * 8) = make_float2(o[nt][2] * inv1, o[nt][3] * inv1);
    }
}

// =================================================================
extern "C" void kernel_launch(void* const* d_in, const int* in_sizes, int n_in,
                              void* d_out, int out_size)
{
    const float* x     = (const float*)d_in[0];
    const float* rph   = (const float*)d_in[1];
    const float* rpw   = (const float*)d_in[2];
    const float* qkvw  = (const float*)d_in[3];
    const float* qkvb  = (const float*)d_in[4];
    const float* projw = (const float*)d_in[5];
    const float* projb = (const float*)d_in[6];
    float* out = (float*)d_out;

    cudaFuncSetAttribute(flash_tc,   cudaFuncAttributeMaxDynamicSharedMemorySize, FLASH_TC_SMEM);
    cudaFuncSetAttribute(rel_kernel, cudaFuncAttributeMaxDynamicSharedMemorySize, REL_SMEM);

    // 1) QKV projection + head split (tf32 tensor cores)
    gemm_tc<0><<<dim3(2304 / 128, MROWS / 128), dim3(256)>>>(x, qkvw, qkvb, nullptr, 2304, DIMM);
    // 2) rel-pos bias tables
    rel_kernel<<<dim3(GRID_H, BHN), dim3(256), REL_SMEM>>>(rph, rpw);
    // 3) fused flash attention (tf32 tensor cores, 128-q tile, prefetch)
    flash_tc<<<dim3(NSEQ / 128, BHN), dim3(256), FLASH_TC_SMEM>>>();
    // 4) output projection (tf32 tensor cores)
    gemm_tc<1><<<dim3(DIMM / 128, MROWS / 128), dim3(256)>>>(nullptr, projw, projb, out, DIMM, DIMM);
}